// round 7
// baseline (speedup 1.0000x reference)
#include <cuda_runtime.h>
#include <cstdint>

#define V_N 65536
#define E_N 4096
#define P_N 4096
#define T_N 512
#define SENTF 1000000000.0f
#define BIGF  1e30f
#define INFF  __int_as_float(0x7f800000)

#define PT_BLOCKS 256          // 256 blocks * 4 warps * 4 points = 4096

// Scratch (device globals: no allocations allowed)
__device__ float2 g_passA[E_N];   // (xmn, xmx)
__device__ float4 g_passB[E_N];   // (ymn, ymx, -b*w, w)   w = 1/a
__device__ float2 g_ab[E_N];      // (a, b)
__device__ float4 g_tbl[T_N];     // TableR cols 3..6
__device__ float  g_m[P_N];
__device__ int    g_valid[P_N];
__device__ int    g_done = 0;     // last-block counter (reset each launch)

// ---------------------------------------------------------------------------
// K1: per-edge precompute + table extraction
// ---------------------------------------------------------------------------
__global__ void __launch_bounds__(128) prep_kernel(
        const float* __restrict__ verts,
        const float* __restrict__ tableR,
        const int*   __restrict__ edges) {
    int e = blockIdx.x * blockDim.x + threadIdx.x;
    if (e < T_N) {
        const float* r = tableR + e * 7;
        g_tbl[e] = make_float4(r[3], r[4], r[5], r[6]);
    }
    if (e < E_N) {
        int i0 = edges[2 * e + 0];
        int i1 = edges[2 * e + 1];
        float x0 = verts[3 * i0 + 0], y0 = verts[3 * i0 + 1];
        float x1 = verts[3 * i1 + 0], y1 = verts[3 * i1 + 1];
        float a = (y0 - y1) / (x0 - x1);                 // IEEE div (matches ref)
        float b = __fsub_rn(y0, __fmul_rn(a, x0));       // no FMA contraction
        float w = 1.0f / a;
        float nbw = -__fmul_rn(b, w);                    // xi = fma(cy, w, nbw)
        g_passA[e] = make_float2(fminf(x0, x1), fmaxf(x0, x1));
        g_passB[e] = make_float4(fminf(y0, y1), fmaxf(y0, y1), nbw, w);
        g_ab[e]    = make_float2(a, b);
    }
}

// ---------------------------------------------------------------------------
// K2: FOUR points per warp (one edge-stream pass serves 4 points)
//     + fused final scan in the last-finishing block.
//     Block = 128 threads = 4 warps = 16 points. 256 blocks.
// ---------------------------------------------------------------------------
__global__ void __launch_bounds__(128) point_kernel(
        const float* __restrict__ verts,
        const int*   __restrict__ listAll,
        float*       __restrict__ out) {
    const unsigned FULL = 0xffffffffu;
    const int tid  = threadIdx.x;
    const int lane = tid & 31;
    const int warp = tid >> 5;                       // 0..3
    const int pbase = (blockIdx.x * 4 + warp) * 4;   // 4 consecutive points

    float px[4], py[4], cy[4], L1v[4];

    // ---- point coords (same-address broadcast loads) ----
    #pragma unroll
    for (int i = 0; i < 4; i++) {
        int li = __ldg(&listAll[pbase + i]);
        px[i] = __ldg(&verts[3 * li + 0]);
        py[i] = __ldg(&verts[3 * li + 1]);
    }

    // ---- Pass 1 per point: first edge with px strictly in (xmn, xmx) ----
    #pragma unroll
    for (int i = 0; i < 4; i++) {
        int idx = 0x7fffffff;
        for (int e = lane; e < E_N; e += 32) {
            float2 mm = __ldg(&g_passA[e]);
            if (px[i] > mm.x && px[i] < mm.y) { idx = e; break; }
        }
        #pragma unroll
        for (int o = 16; o; o >>= 1)
            idx = min(idx, __shfl_xor_sync(FULL, idx, o));
        if (idx == 0x7fffffff) idx = E_N - 1;
        float2 ab = __ldg(&g_ab[idx]);
        float ey = __fadd_rn(__fmul_rn(ab.x, px[i]), ab.y);   // no FMA contraction
        L1v[i] = fabsf(py[i] - ey);
        cy[i]  = (py[i] + ey) * 0.5f;
    }

    // ---- Pass 2: ONE edge stream, 4 accumulator sets ----
    int   n[4];
    float xmx_[4], xmn_[4], xs_[4], xi_[4];
    #pragma unroll
    for (int i = 0; i < 4; i++) {
        n[i] = 0; xmx_[i] = -SENTF; xmn_[i] = SENTF; xs_[i] = SENTF; xi_[i] = -SENTF;
    }

    #pragma unroll 4
    for (int e = lane; e < E_N; e += 32) {
        float4 q = __ldg(&g_passB[e]);        // (ymn, ymx, nbw, w)
        #pragma unroll
        for (int i = 0; i < 4; i++) {
            bool c  = (cy[i] > q.x) && (cy[i] < q.y);        // condB
            float xi = fmaf(cy[i], q.w, q.z);                // (cy-b)*w
            bool ge = (xi >= px[i]);
            n[i] += (int)c;
            xmx_[i] = fmaxf(xmx_[i], c ? xi : -SENTF);
            xmn_[i] = fminf(xmn_[i], c ? xi :  SENTF);
            xs_[i]  = fminf(xs_[i],  (c &&  ge) ? xi :  SENTF);
            xi_[i]  = fmaxf(xi_[i],  (c && !ge) ? xi : -SENTF);
        }
    }

    // butterfly reductions (leave totals in all lanes)
    #pragma unroll
    for (int i = 0; i < 4; i++) {
        #pragma unroll
        for (int o = 16; o; o >>= 1) {
            n[i]    +=             __shfl_xor_sync(FULL, n[i],    o);
            xmx_[i] = fmaxf(xmx_[i], __shfl_xor_sync(FULL, xmx_[i], o));
            xmn_[i] = fminf(xmn_[i], __shfl_xor_sync(FULL, xmn_[i], o));
            xs_[i]  = fminf(xs_[i],  __shfl_xor_sync(FULL, xs_[i],  o));
            xi_[i]  = fmaxf(xi_[i],  __shfl_xor_sync(FULL, xi_[i],  o));
        }
    }

    float L2v[4], d1[4], d2[4];
    int valid[4];
    #pragma unroll
    for (int i = 0; i < 4; i++) {
        int hs = xs_[i] <  SENTF;                 // condB => xi in [0,1]
        int hi = xi_[i] > -SENTF;
        valid[i] = (n[i] == 2) || (n[i] > 2 && hs && hi);
        float dx = (n[i] == 2) ? (xmx_[i] - xmn_[i]) : (xs_[i] - xi_[i]);
        L2v[i] = fabsf(dx);
        d1[i]  = fabsf(cy[i] - 1.0f);
        d2[i]  = fabsf(px[i] - 1.0f);
    }

    // ---- Table min: one stream, 4 accumulators ----
    float pm[4] = {INFF, INFF, INFF, INFF};
    #pragma unroll 4
    for (int t = lane; t < T_N; t += 32) {
        float4 r = __ldg(&g_tbl[t]);
        #pragma unroll
        for (int i = 0; i < 4; i++) {
            float al = fabsf(L1v[i] - r.x) + fabsf(L2v[i] - r.y)
                     + fabsf(d1[i]  - r.z) + fabsf(d2[i]  - r.w);
            pm[i] = fminf(pm[i], al);
        }
    }
    #pragma unroll
    for (int i = 0; i < 4; i++) {
        #pragma unroll
        for (int o = 16; o; o >>= 1)
            pm[i] = fminf(pm[i], __shfl_xor_sync(FULL, pm[i], o));
    }

    if (lane == 0) {
        #pragma unroll
        for (int i = 0; i < 4; i++) {
            g_m[pbase + i]     = valid[i] ? pm[i] : BIGF;
            g_valid[pbase + i] = valid[i];
        }
    }

    // ================== fused scan: last block does it ==================
    __shared__ int s_last;
    __threadfence();
    __syncthreads();
    if (tid == 0) {
        int old = atomicAdd(&g_done, 1);
        s_last = (old == (int)gridDim.x - 1);
    }
    __syncthreads();
    if (!s_last) return;

    {   // 128 threads, 32 values each
        __shared__ float s_wtot[4];
        __shared__ float s_sum[4];
        const int base = tid * 32;

        float c[32];
        float run = INFF;
        #pragma unroll
        for (int i = 0; i < 32; i++) {
            run = fminf(run, g_m[base + i]);
            c[i] = run;
        }

        float scan = run;
        #pragma unroll
        for (int o = 1; o < 32; o <<= 1) {
            float v = __shfl_up_sync(FULL, scan, o);
            if (lane >= o) scan = fminf(scan, v);
        }
        if (lane == 31) s_wtot[warp] = scan;
        __syncthreads();

        float wpre = INFF;
        #pragma unroll
        for (int w = 0; w < 4; w++)
            if (w < warp) wpre = fminf(wpre, s_wtot[w]);

        float lpre = __shfl_up_sync(FULL, scan, 1);
        float pre = fminf(wpre, (lane == 0) ? INFF : lpre);

        float acc = 0.0f;
        #pragma unroll
        for (int i = 0; i < 32; i++)
            if (g_valid[base + i]) acc += fminf(pre, c[i]);

        #pragma unroll
        for (int o = 16; o; o >>= 1)
            acc += __shfl_xor_sync(FULL, acc, o);
        if (lane == 0) s_sum[warp] = acc;
        __syncthreads();
        if (tid == 0) {
            out[0] = s_sum[0] + s_sum[1] + s_sum[2] + s_sum[3];
            g_done = 0;                       // reset for next graph replay
        }
    }
}

// ---------------------------------------------------------------------------
extern "C" void kernel_launch(void* const* d_in, const int* in_sizes, int n_in,
                              void* d_out, int out_size) {
    const float* verts   = (const float*)d_in[0];
    const float* tableR  = (const float*)d_in[1];
    const int*   edges   = (const int*)  d_in[2];
    const int*   listAll = (const int*)  d_in[3];

    prep_kernel <<<32,        128>>>(verts, tableR, edges);
    point_kernel<<<PT_BLOCKS, 128>>>(verts, listAll, (float*)d_out);
}

// round 9
// speedup vs baseline: 1.9950x; 1.9950x over previous
#include <cuda_runtime.h>
#include <cstdint>

#define V_N 65536
#define E_N 4096
#define P_N 4096
#define T_N 512
#define SENTF 1000000000.0f
#define BIGF  1e30f
#define INFF  __int_as_float(0x7f800000)

// Scratch (device globals: no allocations allowed)
__device__ float2 g_passA[E_N];   // (xmn, xmx)
__device__ float4 g_passB[E_N];   // (ymn, ymx, -b*w, w)   w = 1/a
__device__ float2 g_ab[E_N];      // (a, b)
__device__ float4 g_tbl[T_N];     // TableR cols 3..6
__device__ float  g_m[P_N];
__device__ int    g_valid[P_N];

// ---------------------------------------------------------------------------
// K1: per-edge precompute + table extraction
// ---------------------------------------------------------------------------
__global__ void __launch_bounds__(64) prep_kernel(
        const float* __restrict__ verts,
        const float* __restrict__ tableR,
        const int*   __restrict__ edges) {
    int e = blockIdx.x * blockDim.x + threadIdx.x;
    if (e < T_N) {
        const float* r = tableR + e * 7;
        g_tbl[e] = make_float4(r[3], r[4], r[5], r[6]);
    }
    if (e < E_N) {
        int i0 = edges[2 * e + 0];
        int i1 = edges[2 * e + 1];
        float x0 = verts[3 * i0 + 0], y0 = verts[3 * i0 + 1];
        float x1 = verts[3 * i1 + 0], y1 = verts[3 * i1 + 1];
        float a = (y0 - y1) / (x0 - x1);                 // IEEE div (matches ref)
        float b = __fsub_rn(y0, __fmul_rn(a, x0));       // no FMA contraction
        float w = 1.0f / a;
        float nbw = -__fmul_rn(b, w);                    // xi = fma(cy, w, nbw)
        g_passA[e] = make_float2(fminf(x0, x1), fmaxf(x0, x1));
        g_passB[e] = make_float4(fminf(y0, y1), fmaxf(y0, y1), nbw, w);
        g_ab[e]    = make_float2(a, b);
    }
}

// ---------------------------------------------------------------------------
// K2: warp-per-point (R5 topology) + predicated-asm pass-2 body (R6 body)
//     Block = 256 threads = 8 warps = 8 points. 512 blocks.
// ---------------------------------------------------------------------------
__global__ void __launch_bounds__(256) point_kernel(
        const float* __restrict__ verts,
        const int*   __restrict__ listAll) {
    const unsigned FULL = 0xffffffffu;
    const int lane = threadIdx.x & 31;
    const int warp = threadIdx.x >> 5;
    const int p = blockIdx.x * 8 + warp;     // 512 blocks * 8 warps

    int li = __ldg(&listAll[p]);
    float px = __ldg(&verts[3 * li + 0]);
    float py = __ldg(&verts[3 * li + 1]);

    // ---- Pass 1: first edge with px strictly inside (xmn, xmx) ----
    int idx = 0x7fffffff;
    for (int e = lane; e < E_N; e += 32) {
        float2 mm = __ldg(&g_passA[e]);
        if (px > mm.x && px < mm.y) { idx = e; break; }   // lane stream ascending
    }
    #pragma unroll
    for (int o = 16; o; o >>= 1)
        idx = min(idx, __shfl_xor_sync(FULL, idx, o));
    if (idx == 0x7fffffff) idx = E_N - 1;

    float2 ab = __ldg(&g_ab[idx]);
    float exposeY = __fadd_rn(__fmul_rn(ab.x, px), ab.y);  // no FMA contraction
    float L1v = fabsf(py - exposeY);
    float cy  = (py + exposeY) * 0.5f;

    // ---- Pass 2: predicated updates, straight from L1 (no smem staging) ----
    int n = 0;
    float xallmx = -SENTF, xallmn = SENTF;
    float xs = SENTF, xinf = -SENTF;
    #pragma unroll 8
    for (int e = lane; e < E_N; e += 32) {
        float4 q = __ldg(&g_passB[e]);        // (ymn, ymx, nbw, w)
        float xi = fmaf(cy, q.w, q.z);        // (cy-b)*w  (<=2 ulp vs ref)
        asm volatile(
            "{\n\t"
            ".reg .pred pc, pg, pl;\n\t"
            "setp.gt.f32 pc, %6, %7;\n\t"          // cy > ymn
            "setp.lt.and.f32 pc, %6, %8, pc;\n\t"  // && cy < ymx
            "@pc add.s32 %4, %4, 1;\n\t"
            "@pc max.f32 %0, %0, %5;\n\t"
            "@pc min.f32 %1, %1, %5;\n\t"
            "setp.ge.and.f32 pg, %5, %9, pc;\n\t"  // condB && xi >= px
            "setp.lt.and.f32 pl, %5, %9, pc;\n\t"  // condB && xi <  px
            "@pg min.f32 %2, %2, %5;\n\t"
            "@pl max.f32 %3, %3, %5;\n\t"
            "}"
            : "+f"(xallmx), "+f"(xallmn), "+f"(xs), "+f"(xinf), "+r"(n)
            : "f"(xi), "f"(cy), "f"(q.x), "f"(q.y), "f"(px));
    }
    #pragma unroll
    for (int o = 16; o; o >>= 1) {
        n      +=              __shfl_xor_sync(FULL, n,      o);
        xallmx = fmaxf(xallmx, __shfl_xor_sync(FULL, xallmx, o));
        xallmn = fminf(xallmn, __shfl_xor_sync(FULL, xallmn, o));
        xs     = fminf(xs,     __shfl_xor_sync(FULL, xs,     o));
        xinf   = fmaxf(xinf,   __shfl_xor_sync(FULL, xinf,   o));
    }

    // condB => xi in [0,1]; presence <=> sentinel moved
    int hs = xs   <  SENTF;
    int hi = xinf > -SENTF;
    int valid = (n == 2) || (n > 2 && hs && hi);
    float dx  = (n == 2) ? (xallmx - xallmn) : (xs - xinf);
    float L2v = fabsf(dx);
    float d1  = fabsf(cy - 1.0f);
    float d2  = fabsf(px - 1.0f);

    // ---- Table min over T=512 rows ----
    float pm = INFF;
    #pragma unroll 4
    for (int t = lane; t < T_N; t += 32) {
        float4 r = __ldg(&g_tbl[t]);
        float al = fabsf(L1v - r.x) + fabsf(L2v - r.y)
                 + fabsf(d1  - r.z) + fabsf(d2  - r.w);
        pm = fminf(pm, al);
    }
    #pragma unroll
    for (int o = 16; o; o >>= 1)
        pm = fminf(pm, __shfl_xor_sync(FULL, pm, o));

    if (lane == 0) {
        g_m[p]     = valid ? pm : BIGF;
        g_valid[p] = valid;
    }
}

// ---------------------------------------------------------------------------
// K3: cummin + masked sum (1 block, 256 threads, shuffle-based scan)
// ---------------------------------------------------------------------------
__global__ void __launch_bounds__(256) scan_kernel(float* __restrict__ out) {
    const unsigned FULL = 0xffffffffu;
    __shared__ float s_wtot[8];
    __shared__ float s_sum[8];
    const int tid  = threadIdx.x;
    const int lane = tid & 31;
    const int wid  = tid >> 5;
    const int base = tid * 16;

    float c[16];
    float run = INFF;
    #pragma unroll
    for (int i = 0; i < 16; i++) {
        run = fminf(run, g_m[base + i]);
        c[i] = run;
    }

    float scan = run;
    #pragma unroll
    for (int o = 1; o < 32; o <<= 1) {
        float v = __shfl_up_sync(FULL, scan, o);
        if (lane >= o) scan = fminf(scan, v);
    }
    if (lane == 31) s_wtot[wid] = scan;
    __syncthreads();

    float wpre = INFF;
    #pragma unroll
    for (int w = 0; w < 8; w++)
        if (w < wid) wpre = fminf(wpre, s_wtot[w]);

    float lpre = __shfl_up_sync(FULL, scan, 1);
    float pre = fminf(wpre, (lane == 0) ? INFF : lpre);

    float acc = 0.0f;
    #pragma unroll
    for (int i = 0; i < 16; i++)
        if (g_valid[base + i]) acc += fminf(pre, c[i]);

    #pragma unroll
    for (int o = 16; o; o >>= 1)
        acc += __shfl_xor_sync(FULL, acc, o);
    if (lane == 0) s_sum[wid] = acc;
    __syncthreads();
    if (tid == 0) {
        float s = 0.0f;
        #pragma unroll
        for (int w = 0; w < 8; w++) s += s_sum[w];
        out[0] = s;
    }
}

// ---------------------------------------------------------------------------
extern "C" void kernel_launch(void* const* d_in, const int* in_sizes, int n_in,
                              void* d_out, int out_size) {
    const float* verts   = (const float*)d_in[0];
    const float* tableR  = (const float*)d_in[1];
    const int*   edges   = (const int*)  d_in[2];
    const int*   listAll = (const int*)  d_in[3];

    prep_kernel <<<64,   64>>>(verts, tableR, edges);
    point_kernel<<<512, 256>>>(verts, listAll);
    scan_kernel <<<1,   256>>>((float*)d_out);
}